// round 9
// baseline (speedup 1.0000x reference)
#include <cuda_runtime.h>
#include <cstdint>

// Problem constants
#define NN 200000
#define D  128
#define P  4096
#define R  4
#define T  3
#define K  16

#define KSPLIT 16
#define PD (P * D)

// ---------------------------------------------------------------------------
// Scratch (static __device__ — no runtime allocation)
// ---------------------------------------------------------------------------
__device__ __align__(16) float g_u[T * D];          // u_t = W_phi[t] @ zn
__device__ __align__(16) float g_v[T * D];          // v_t = W_phi[t] @ zs
__device__ __align__(16) float g_bias2[D];          // 2 * sum_r W_beta_b[r][e]
__device__ __align__(16) float g_y1[NN];            // x[n] . u_{ty[n]}
__device__ __align__(16) float g_y2[NN];            // x[n] . v_{ty[n]}
__device__ __align__(16) float g_g[P * R * D];      // sum_s h_agg[p,s,r,:]
__device__ __align__(16) float g_part[KSPLIT * PD]; // split-K partials (33.5 MB)

// ---------------------------------------------------------------------------
// Kernel 1: prep — u, v vectors and bias2. grid=4 blocks x 128 threads.
// ---------------------------------------------------------------------------
__global__ void prep_kernel(const float* __restrict__ W_phi,
                            const float* __restrict__ W_zeta,
                            const float* __restrict__ W_beta_b) {
    int b = blockIdx.x;
    int tid = threadIdx.x;
    if (b < T) {
        const float* wrow = W_phi + (b * D + tid) * D;
        float au = 0.f, av = 0.f;
#pragma unroll 8
        for (int e = 0; e < D; e++) {
            float w = wrow[e];
            au = fmaf(w, W_zeta[e], au);
            av = fmaf(w, W_zeta[D + e], av);
        }
        g_u[b * D + tid] = au;
        g_v[b * D + tid] = av;
    } else {
        float s = 0.f;
#pragma unroll
        for (int r = 0; r < R; r++) s += W_beta_b[r * D + tid];
        g_bias2[tid] = 2.f * s;
    }
}

// ---------------------------------------------------------------------------
// Kernel 2: ypass — per-node dots y1 = x.u_ty, y2 = x.v_ty for ALL nodes.
// Warp per node, 8 warps/block. grid = 25000 (exactly 200000 nodes).
// ---------------------------------------------------------------------------
__global__ __launch_bounds__(256) void ypass_kernel(
    const float* __restrict__ x,
    const int* __restrict__ types) {

    int lane = threadIdx.x & 31;
    int node = blockIdx.x * 8 + (threadIdx.x >> 5);
    int ty = types[node];
    float4 xr = *(const float4*)(x + (size_t)node * D + lane * 4);
    float4 u4 = *(const float4*)(g_u + ty * D + lane * 4);
    float4 v4 = *(const float4*)(g_v + ty * D + lane * 4);
    float d = xr.x * u4.x + xr.y * u4.y + xr.z * u4.z + xr.w * u4.w;
    float e = xr.x * v4.x + xr.y * v4.y + xr.z * v4.z + xr.w * v4.w;
#pragma unroll
    for (int off = 16; off; off >>= 1) {
        d += __shfl_xor_sync(0xffffffffu, d, off);
        e += __shfl_xor_sync(0xffffffffu, e, off);
    }
    if (lane == 0) {
        g_y1[node] = d;
        g_y2[node] = e;
    }
}

// ---------------------------------------------------------------------------
// Kernel 3: main — gather + softmax + aggregate. Block = pair p (128 thr),
// warp w = relation r. No smem, no barriers, no reduction butterflies:
// e_n comes from the precomputed y1 gather; softmax normalization deferred.
// grid = 4096.
// ---------------------------------------------------------------------------
__global__ __launch_bounds__(128) void main_kernel(
    const float* __restrict__ x,
    const int* __restrict__ pairs,
    const int* __restrict__ nbr,
    const float* __restrict__ dt) {

    int p = blockIdx.x;
    int w = threadIdx.x >> 5;    // r
    int lane = threadIdx.x & 31;

    float es0 = g_y2[pairs[2 * p]];
    float es1 = g_y2[pairs[2 * p + 1]];

    float4 hacc = make_float4(0.f, 0.f, 0.f, 0.f);
    int base0 = (p * 2 * R + w) * K;

#pragma unroll
    for (int s = 0; s < 2; s++) {
        int base = base0 + s * (R * K);
        float es = s ? es1 : es0;

        int ni = 0;
        float ex = 0.f;
        if (lane < 16) {
            ni = nbr[base + lane];
            float edt = __expf(-dt[base + lane]);
            float w1 = g_y1[ni];
            ex = __expf((w1 + es) * edt);
        }

        float sum = 0.f;
        float4 hs = make_float4(0.f, 0.f, 0.f, 0.f);

#pragma unroll
        for (int b = 0; b < 2; b++) {
            float4 xv[8];
#pragma unroll
            for (int j = 0; j < 8; j++) {
                int nik = __shfl_sync(0xffffffffu, ni, b * 8 + j);
                xv[j] = *(const float4*)(x + (size_t)nik * D + lane * 4);
            }
#pragma unroll
            for (int j = 0; j < 8; j++) {
                float exk = __shfl_sync(0xffffffffu, ex, b * 8 + j);
                sum += exk;
                hs.x = fmaf(exk, xv[j].x, hs.x);
                hs.y = fmaf(exk, xv[j].y, hs.y);
                hs.z = fmaf(exk, xv[j].z, hs.z);
                hs.w = fmaf(exk, xv[j].w, hs.w);
            }
        }
        float inv = __fdividef(1.f, sum);
        hacc.x = fmaf(inv, hs.x, hacc.x);
        hacc.y = fmaf(inv, hs.y, hacc.y);
        hacc.z = fmaf(inv, hs.z, hacc.z);
        hacc.w = fmaf(inv, hs.w, hacc.w);
    }

    *(float4*)(g_g + (size_t)(p * R + w) * D + lane * 4) = hacc;
}

// ---------------------------------------------------------------------------
// Kernel 4: split-K GEMM partials. Block tile 32M x 128N x 32K, single smem
// stage, 128 threads, micro-tile 4M x 8N. grid = 128 Mtiles * 16 Kslices
// = 2048 blocks (~14/SM — latency actually hidden, unlike 2-stage/512-block).
// ---------------------------------------------------------------------------
#define GM 32
#define GK 32

__global__ __launch_bounds__(128) void gemm_kernel(const float* __restrict__ Wb) {
    int bx = blockIdx.x;
    int mb = bx & 127;
    int ks = bx >> 7;
    int p0 = mb * GM;
    int kbase = ks * GK;
    int tid = threadIdx.x;

    __shared__ __align__(16) float As[GK][GM];    // 4 KB  (k-major)
    __shared__ __align__(16) float Bs[GK][D];     // 16 KB

    // fills: A — thread loads 8 floats of one row; B — 32 floats of one k-row
    int am = tid >> 2;              // 0..31
    int ak = (tid & 3) * 8;         // 0,8,16,24
    int bk = tid >> 2;              // 0..31
    int bn = (tid & 3) * 32;        // 0,32,64,96

    const float* ga = g_g + (size_t)(p0 + am) * (R * D) + kbase + ak;
    float4 a0 = *(const float4*)ga;
    float4 a1 = *(const float4*)(ga + 4);
    const float* gb = Wb + (size_t)(kbase + bk) * D + bn;
    float4 b0 = *(const float4*)gb;
    float4 b1 = *(const float4*)(gb + 4);
    float4 b2 = *(const float4*)(gb + 8);
    float4 b3 = *(const float4*)(gb + 12);
    float4 b4 = *(const float4*)(gb + 16);
    float4 b5 = *(const float4*)(gb + 20);
    float4 b6 = *(const float4*)(gb + 24);
    float4 b7 = *(const float4*)(gb + 28);

    As[ak + 0][am] = a0.x; As[ak + 1][am] = a0.y;
    As[ak + 2][am] = a0.z; As[ak + 3][am] = a0.w;
    As[ak + 4][am] = a1.x; As[ak + 5][am] = a1.y;
    As[ak + 6][am] = a1.z; As[ak + 7][am] = a1.w;
    *(float4*)&Bs[bk][bn]      = b0;
    *(float4*)&Bs[bk][bn + 4]  = b1;
    *(float4*)&Bs[bk][bn + 8]  = b2;
    *(float4*)&Bs[bk][bn + 12] = b3;
    *(float4*)&Bs[bk][bn + 16] = b4;
    *(float4*)&Bs[bk][bn + 20] = b5;
    *(float4*)&Bs[bk][bn + 24] = b6;
    *(float4*)&Bs[bk][bn + 28] = b7;
    __syncthreads();

    // compute: 8x16 thread grid, micro 4M x 8N
    int tm = (tid >> 4) * 4;
    int tn = (tid & 15) * 8;

    unsigned long long acc[4][4];
#pragma unroll
    for (int mi = 0; mi < 4; mi++)
#pragma unroll
        for (int j = 0; j < 4; j++) acc[mi][j] = 0ull;

#pragma unroll 8
    for (int k = 0; k < GK; k++) {
        float4 fa = *(const float4*)&As[k][tm];          // broadcast
        ulonglong2 p01 = *(const ulonglong2*)&Bs[k][tn];
        ulonglong2 p23 = *(const ulonglong2*)&Bs[k][tn + 4];
        float av[4] = {fa.x, fa.y, fa.z, fa.w};
#pragma unroll
        for (int mi = 0; mi < 4; mi++) {
            unsigned long long ap;
            asm("mov.b64 %0, {%1, %2};" : "=l"(ap) : "f"(av[mi]), "f"(av[mi]));
            asm("fma.rn.f32x2 %0, %1, %2, %0;" : "+l"(acc[mi][0]) : "l"(ap), "l"(p01.x));
            asm("fma.rn.f32x2 %0, %1, %2, %0;" : "+l"(acc[mi][1]) : "l"(ap), "l"(p01.y));
            asm("fma.rn.f32x2 %0, %1, %2, %0;" : "+l"(acc[mi][2]) : "l"(ap), "l"(p23.x));
            asm("fma.rn.f32x2 %0, %1, %2, %0;" : "+l"(acc[mi][3]) : "l"(ap), "l"(p23.y));
        }
    }

    float* dst_base = g_part + (size_t)ks * PD;
#pragma unroll
    for (int mi = 0; mi < 4; mi++) {
        float c[8];
#pragma unroll
        for (int j = 0; j < 4; j++) {
            float lo, hi;
            asm("mov.b64 {%0, %1}, %2;" : "=f"(lo), "=f"(hi) : "l"(acc[mi][j]));
            c[2 * j] = lo;
            c[2 * j + 1] = hi;
        }
        float* dst = dst_base + (size_t)(p0 + tm + mi) * D + tn;
        *(float4*)dst       = make_float4(c[0], c[1], c[2], c[3]);
        *(float4*)(dst + 4) = make_float4(c[4], c[5], c[6], c[7]);
    }
}

// ---------------------------------------------------------------------------
// Kernel 5: reduce split-K partials + bias + sigmoid. grid=1024 x 128,
// one float4 per thread.
// ---------------------------------------------------------------------------
__global__ __launch_bounds__(128) void reduce_kernel(float* __restrict__ out) {
    int idx = blockIdx.x * 128 + threadIdx.x;   // float4 index
    int off = idx * 4;
    float4 a = *(const float4*)(g_part + off);
#pragma unroll
    for (int ks = 1; ks < KSPLIT; ks++) {
        float4 b = *(const float4*)(g_part + (size_t)ks * PD + off);
        a.x += b.x; a.y += b.y; a.z += b.z; a.w += b.w;
    }
    float4 bias = *(const float4*)&g_bias2[off & (D - 1)];
    a.x = 0.125f * (a.x + bias.x);
    a.y = 0.125f * (a.y + bias.y);
    a.z = 0.125f * (a.z + bias.z);
    a.w = 0.125f * (a.w + bias.w);
    a.x = __fdividef(1.f, 1.f + __expf(-a.x));
    a.y = __fdividef(1.f, 1.f + __expf(-a.y));
    a.z = __fdividef(1.f, 1.f + __expf(-a.z));
    a.w = __fdividef(1.f, 1.f + __expf(-a.w));
    *(float4*)(out + off) = a;
}

// ---------------------------------------------------------------------------
// Launch
// ---------------------------------------------------------------------------
extern "C" void kernel_launch(void* const* d_in, const int* in_sizes, int n_in,
                              void* d_out, int out_size) {
    const float* node_embeds   = (const float*)d_in[0];
    const int*   node_pairs    = (const int*)d_in[1];
    const int*   node_type_ids = (const int*)d_in[2];
    const int*   neighbor_idx  = (const int*)d_in[3];
    const float* delta_t       = (const float*)d_in[4];
    const float* W_phi         = (const float*)d_in[5];
    const float* W_zeta        = (const float*)d_in[6];
    const float* W_beta_w      = (const float*)d_in[7];
    const float* W_beta_b      = (const float*)d_in[8];
    float* out = (float*)d_out;

    prep_kernel<<<4, 128>>>(W_phi, W_zeta, W_beta_b);
    ypass_kernel<<<NN / 8, 256>>>(node_embeds, node_type_ids);
    main_kernel<<<P, 128>>>(node_embeds, node_pairs, neighbor_idx, delta_t);
    gemm_kernel<<<(P / GM) * KSPLIT, 128>>>(W_beta_w);
    reduce_kernel<<<(PD / 4) / 128, 128>>>(out);
}

// round 10
// speedup vs baseline: 1.3381x; 1.3381x over previous
#include <cuda_runtime.h>
#include <cstdint>

// Problem constants
#define NN 200000
#define D  128
#define P  4096
#define R  4
#define T  3
#define K  16

#define KSPLIT 16
#define PD (P * D)

// ---------------------------------------------------------------------------
// Scratch (static __device__ — no runtime allocation)
// ---------------------------------------------------------------------------
__device__ __align__(16) float g_u[T * D];          // u_t = W_phi[t] @ zn
__device__ __align__(16) float g_v[T * D];          // v_t = W_phi[t] @ zs
__device__ __align__(16) float g_bias2[D];          // 2 * sum_r W_beta_b[r][e]
__device__ __align__(16) float g_es[P * 2];         // e_s per (p,s)
__device__ __align__(16) float g_g[P * R * D];      // sum_s h_agg[p,s,r,:]
__device__ __align__(16) float g_part[KSPLIT * PD]; // split-K partials (33.5 MB)

// ---------------------------------------------------------------------------
// Kernel 1: prep — u, v vectors and bias2. grid=4 blocks x 128 threads.
// ---------------------------------------------------------------------------
__global__ void prep_kernel(const float* __restrict__ W_phi,
                            const float* __restrict__ W_zeta,
                            const float* __restrict__ W_beta_b) {
    int b = blockIdx.x;
    int tid = threadIdx.x;
    if (b < T) {
        const float* wrow = W_phi + (b * D + tid) * D;
        float au = 0.f, av = 0.f;
#pragma unroll 8
        for (int e = 0; e < D; e++) {
            float w = wrow[e];
            au = fmaf(w, W_zeta[e], au);
            av = fmaf(w, W_zeta[D + e], av);
        }
        g_u[b * D + tid] = au;
        g_v[b * D + tid] = av;
    } else {
        float s = 0.f;
#pragma unroll
        for (int r = 0; r < R; r++) s += W_beta_b[r * D + tid];
        g_bias2[tid] = 2.f * s;
    }
}

// ---------------------------------------------------------------------------
// Kernel 2: e_s per (p,s). One warp per pair-slot. grid=2048 x 128.
// ---------------------------------------------------------------------------
__global__ void es_kernel(const float* __restrict__ x,
                          const int* __restrict__ node_pairs,
                          const int* __restrict__ types) {
    int tid = threadIdx.x;
    int lane = tid & 31;
    int gw = blockIdx.x * 4 + (tid >> 5);   // ps index, 0..8191
    int node = node_pairs[gw];
    int t = types[node];
    const float4 x4 = *(const float4*)(x + (size_t)node * D + lane * 4);
    const float4 v4 = *(const float4*)(g_v + t * D + lane * 4);
    float part = x4.x * v4.x + x4.y * v4.y + x4.z * v4.z + x4.w * v4.w;
#pragma unroll
    for (int off = 16; off; off >>= 1)
        part += __shfl_xor_sync(0xffffffffu, part, off);
    if (lane == 0) g_es[gw] = part;
}

// ---------------------------------------------------------------------------
// Kernel 3: main — gather + softmax + aggregate. Block = pair p (128 thr),
// warp w = relation r; no cross-warp communication. Both s-iterations'
// neighbor idx/type/dt are loaded UP FRONT so the two scattered-load rounds
// overlap. Softmax normalization deferred to the end of each s. grid = 4096.
// ---------------------------------------------------------------------------
__global__ __launch_bounds__(128) void main_kernel(
    const float* __restrict__ x,
    const int* __restrict__ types,
    const int* __restrict__ nbr,
    const float* __restrict__ dt) {

    int p = blockIdx.x;
    int tid = threadIdx.x;
    int w = tid >> 5;       // r
    int lane = tid & 31;

    __shared__ __align__(16) float s_u[T * D];   // 1.5 KB
    s_u[tid]       = g_u[tid];
    s_u[tid + 128] = g_u[tid + 128];
    s_u[tid + 256] = g_u[tid + 256];

    int base0 = (p * 2 * R + w) * K;
    int base1 = base0 + R * K;

    int ni0 = 0, ni1 = 0, ty0 = 0, ty1 = 0;
    float edt0 = 0.f, edt1 = 0.f;
    if (lane < 16) {
        ni0 = nbr[base0 + lane];
        ni1 = nbr[base1 + lane];
        edt0 = __expf(-dt[base0 + lane]);
        edt1 = __expf(-dt[base1 + lane]);
        ty0 = types[ni0];
        ty1 = types[ni1];
    }
    float es0 = g_es[p * 2];
    float es1 = g_es[p * 2 + 1];
    __syncthreads();                 // s_u staged

    float4 hacc = make_float4(0.f, 0.f, 0.f, 0.f);

#pragma unroll
    for (int s = 0; s < 2; s++) {
        int   ni  = s ? ni1  : ni0;
        int   ty  = s ? ty1  : ty0;
        float edt = s ? edt1 : edt0;
        float es  = s ? es1  : es0;

        float sum = 0.f;
        float4 hs = make_float4(0.f, 0.f, 0.f, 0.f);

#pragma unroll
        for (int b = 0; b < 2; b++) {        // two batches of 8 neighbors
            float4 xv[8];
#pragma unroll
            for (int j = 0; j < 8; j++) {
                int nik = __shfl_sync(0xffffffffu, ni, b * 8 + j);
                xv[j] = *(const float4*)(x + (size_t)nik * D + lane * 4);
            }
#pragma unroll
            for (int j = 0; j < 8; j++) {
                int k = b * 8 + j;
                int tyk = __shfl_sync(0xffffffffu, ty, k);
                const float4 u4 = *(const float4*)&s_u[tyk * D + lane * 4];
                float d = xv[j].x * u4.x + xv[j].y * u4.y +
                          xv[j].z * u4.z + xv[j].w * u4.w;
#pragma unroll
                for (int off = 16; off; off >>= 1)
                    d += __shfl_xor_sync(0xffffffffu, d, off);
                float edtk = __shfl_sync(0xffffffffu, edt, k);
                float ex = __expf((d + es) * edtk);   // same value all lanes
                sum += ex;
                hs.x = fmaf(ex, xv[j].x, hs.x);
                hs.y = fmaf(ex, xv[j].y, hs.y);
                hs.z = fmaf(ex, xv[j].z, hs.z);
                hs.w = fmaf(ex, xv[j].w, hs.w);
            }
        }
        float inv = __fdividef(1.f, sum);
        hacc.x = fmaf(inv, hs.x, hacc.x);
        hacc.y = fmaf(inv, hs.y, hacc.y);
        hacc.z = fmaf(inv, hs.z, hacc.z);
        hacc.w = fmaf(inv, hs.w, hacc.w);
    }

    *(float4*)(g_g + (size_t)(p * R + w) * D + lane * 4) = hacc;
}

// ---------------------------------------------------------------------------
// Kernel 4: split-K GEMM partials. Block tile 128M x 128N x 32K, 256 threads,
// micro-tile 8M x 8N (1 B/FMA smem traffic), single smem stage.
// grid = 32 Mtiles * 16 Kslices = 512 blocks (8 warps each, ~16 warps/SM).
// Smem rows padded to 132 floats: conflict-free fills and reads.
// ---------------------------------------------------------------------------
#define GM 128
#define GK 32
#define SP 132   // padded row length

__global__ __launch_bounds__(256) void gemm_kernel(const float* __restrict__ Wb) {
    int bx = blockIdx.x;
    int mb = bx & 31;
    int ks = bx >> 5;
    int p0 = mb * GM;
    int kbase = ks * GK;
    int tid = threadIdx.x;

    __shared__ __align__(16) float As[GK * SP];   // k-major, 16.9 KB
    __shared__ __align__(16) float Bs[GK * SP];   // 16.9 KB

    // fill A: thread loads 16 floats of one g row, stores transposed
    {
        int am = tid >> 1;                // 0..127
        int ak = (tid & 1) * 16;          // 0 or 16
        const float* ga = g_g + (size_t)(p0 + am) * (R * D) + kbase + ak;
        float4 a0 = *(const float4*)ga;
        float4 a1 = *(const float4*)(ga + 4);
        float4 a2 = *(const float4*)(ga + 8);
        float4 a3 = *(const float4*)(ga + 12);
        float av[16] = {a0.x, a0.y, a0.z, a0.w, a1.x, a1.y, a1.z, a1.w,
                        a2.x, a2.y, a2.z, a2.w, a3.x, a3.y, a3.z, a3.w};
#pragma unroll
        for (int i = 0; i < 16; i++)
            As[(ak + i) * SP + am] = av[i];
    }
    // fill B: thread loads 16 floats of one Wb k-row
    {
        int bk = tid >> 3;                // 0..31
        int bn = (tid & 7) * 16;          // 0..112
        const float* gb = Wb + (size_t)(kbase + bk) * D + bn;
        float4 b0 = *(const float4*)gb;
        float4 b1 = *(const float4*)(gb + 4);
        float4 b2 = *(const float4*)(gb + 8);
        float4 b3 = *(const float4*)(gb + 12);
        float* brow = Bs + bk * SP + bn;
        *(float4*)brow        = b0;
        *(float4*)(brow + 4)  = b1;
        *(float4*)(brow + 8)  = b2;
        *(float4*)(brow + 12) = b3;
    }
    __syncthreads();

    // compute: 16x16 thread grid, micro 8M x 8N
    int tm = (tid >> 4) * 8;
    int tn = (tid & 15) * 8;

    unsigned long long acc[8][4];
#pragma unroll
    for (int mi = 0; mi < 8; mi++)
#pragma unroll
        for (int j = 0; j < 4; j++) acc[mi][j] = 0ull;

#pragma unroll 4
    for (int k = 0; k < GK; k++) {
        const float* arow = As + k * SP + tm;
        float4 fa0 = *(const float4*)arow;
        float4 fa1 = *(const float4*)(arow + 4);
        const float* brow = Bs + k * SP + tn;
        ulonglong2 b01 = *(const ulonglong2*)brow;
        ulonglong2 b23 = *(const ulonglong2*)(brow + 4);
        float av[8] = {fa0.x, fa0.y, fa0.z, fa0.w,
                       fa1.x, fa1.y, fa1.z, fa1.w};
#pragma unroll
        for (int mi = 0; mi < 8; mi++) {
            unsigned long long ap;
            asm("mov.b64 %0, {%1, %2};" : "=l"(ap) : "f"(av[mi]), "f"(av[mi]));
            asm("fma.rn.f32x2 %0, %1, %2, %0;" : "+l"(acc[mi][0]) : "l"(ap), "l"(b01.x));
            asm("fma.rn.f32x2 %0, %1, %2, %0;" : "+l"(acc[mi][1]) : "l"(ap), "l"(b01.y));
            asm("fma.rn.f32x2 %0, %1, %2, %0;" : "+l"(acc[mi][2]) : "l"(ap), "l"(b23.x));
            asm("fma.rn.f32x2 %0, %1, %2, %0;" : "+l"(acc[mi][3]) : "l"(ap), "l"(b23.y));
        }
    }

    float* dst_base = g_part + (size_t)ks * PD;
#pragma unroll
    for (int mi = 0; mi < 8; mi++) {
        float c[8];
#pragma unroll
        for (int j = 0; j < 4; j++) {
            float lo, hi;
            asm("mov.b64 {%0, %1}, %2;" : "=f"(lo), "=f"(hi) : "l"(acc[mi][j]));
            c[2 * j] = lo;
            c[2 * j + 1] = hi;
        }
        float* dst = dst_base + (size_t)(p0 + tm + mi) * D + tn;
        *(float4*)dst       = make_float4(c[0], c[1], c[2], c[3]);
        *(float4*)(dst + 4) = make_float4(c[4], c[5], c[6], c[7]);
    }
}

// ---------------------------------------------------------------------------
// Kernel 5: reduce split-K partials + bias + sigmoid. grid=1024 x 128,
// one float4 per thread.
// ---------------------------------------------------------------------------
__global__ __launch_bounds__(128) void reduce_kernel(float* __restrict__ out) {
    int idx = blockIdx.x * 128 + threadIdx.x;   // float4 index
    int off = idx * 4;
    float4 a = *(const float4*)(g_part + off);
#pragma unroll
    for (int ks = 1; ks < KSPLIT; ks++) {
        float4 b = *(const float4*)(g_part + (size_t)ks * PD + off);
        a.x += b.x; a.y += b.y; a.z += b.z; a.w += b.w;
    }
    float4 bias = *(const float4*)&g_bias2[off & (D - 1)];
    a.x = 0.125f * (a.x + bias.x);
    a.y = 0.125f * (a.y + bias.y);
    a.z = 0.125f * (a.z + bias.z);
    a.w = 0.125f * (a.w + bias.w);
    a.x = __fdividef(1.f, 1.f + __expf(-a.x));
    a.y = __fdividef(1.f, 1.f + __expf(-a.y));
    a.z = __fdividef(1.f, 1.f + __expf(-a.z));
    a.w = __fdividef(1.f, 1.f + __expf(-a.w));
    *(float4*)(out + off) = a;
}

// ---------------------------------------------------------------------------
// Launch
// ---------------------------------------------------------------------------
extern "C" void kernel_launch(void* const* d_in, const int* in_sizes, int n_in,
                              void* d_out, int out_size) {
    const float* node_embeds   = (const float*)d_in[0];
    const int*   node_pairs    = (const int*)d_in[1];
    const int*   node_type_ids = (const int*)d_in[2];
    const int*   neighbor_idx  = (const int*)d_in[3];
    const float* delta_t       = (const float*)d_in[4];
    const float* W_phi         = (const float*)d_in[5];
    const float* W_zeta        = (const float*)d_in[6];
    const float* W_beta_w      = (const float*)d_in[7];
    const float* W_beta_b      = (const float*)d_in[8];
    float* out = (float*)d_out;

    prep_kernel<<<4, 128>>>(W_phi, W_zeta, W_beta_b);
    es_kernel<<<(P * 2) / 4, 128>>>(node_embeds, node_pairs, node_type_ids);
    main_kernel<<<P, 128>>>(node_embeds, node_type_ids, neighbor_idx, delta_t);
    gemm_kernel<<<(P / GM) * KSPLIT, 256>>>(W_beta_w);
    reduce_kernel<<<(PD / 4) / 128, 128>>>(out);
}

// round 12
// speedup vs baseline: 1.4566x; 1.0885x over previous
#include <cuda_runtime.h>
#include <cuda_bf16.h>
#include <cstdint>

// Problem constants
#define NN 200000
#define D  128
#define P  4096
#define R  4
#define T  3
#define K  16

// ---------------------------------------------------------------------------
// Scratch (static __device__ — no runtime allocation)
// ---------------------------------------------------------------------------
__device__ __align__(16) float g_u[T * D];          // u_t = W_phi[t] @ zn
__device__ __align__(16) float g_v[T * D];          // v_t = W_phi[t] @ zs
__device__ __align__(16) float g_bias2[D];          // 2 * sum_r W_beta_b[r][e]
__device__ __align__(16) float g_es[P * 2];         // e_s per (p,s)
__device__ __align__(16) float g_g[P * R * D];      // sum_s h_agg[p,s,r,:]
// Packed bf16 B fragments for m16n8k16: row = kt*4 + t (kt 0..31, t 0..3),
// col = n (0..127). .x = {B[kt*16+2t][n], B[kt*16+2t+1][n]},
// .y = same with k+8. One LDS.64 = both B regs of one mma.
__device__ __align__(16) uint2 g_wbQ[128 * 128];

// ---------------------------------------------------------------------------
// Kernel 1: prep — u, v vectors and bias2. grid=4 blocks x 128 threads.
// ---------------------------------------------------------------------------
__global__ void prep_kernel(const float* __restrict__ W_phi,
                            const float* __restrict__ W_zeta,
                            const float* __restrict__ W_beta_b) {
    int b = blockIdx.x;
    int tid = threadIdx.x;
    if (b < T) {
        const float* wrow = W_phi + (b * D + tid) * D;
        float au = 0.f, av = 0.f;
#pragma unroll 8
        for (int e = 0; e < D; e++) {
            float w = wrow[e];
            au = fmaf(w, W_zeta[e], au);
            av = fmaf(w, W_zeta[D + e], av);
        }
        g_u[b * D + tid] = au;
        g_v[b * D + tid] = av;
    } else {
        float s = 0.f;
#pragma unroll
        for (int r = 0; r < R; r++) s += W_beta_b[r * D + tid];
        g_bias2[tid] = 2.f * s;
    }
}

// ---------------------------------------------------------------------------
// Kernel 1b: pack W_beta_w [512][128] fp32 -> g_wbQ fragments (bf16).
// grid=64 x 256. 16384 entries.
// ---------------------------------------------------------------------------
__global__ void wbq_kernel(const float* __restrict__ Wb) {
    int idx = blockIdx.x * 256 + threadIdx.x;   // row*128 + n
    int row = idx >> 7;        // 0..127 = kt*4 + t
    int n = idx & 127;
    int kt = row >> 2, t = row & 3;
    int k0 = kt * 16 + t * 2;
    float w00 = Wb[k0 * D + n];
    float w01 = Wb[(k0 + 1) * D + n];
    float w10 = Wb[(k0 + 8) * D + n];
    float w11 = Wb[(k0 + 9) * D + n];
    uint32_t b0, b1;
    asm("cvt.rn.bf16x2.f32 %0, %1, %2;" : "=r"(b0) : "f"(w01), "f"(w00));
    asm("cvt.rn.bf16x2.f32 %0, %1, %2;" : "=r"(b1) : "f"(w11), "f"(w10));
    g_wbQ[idx] = make_uint2(b0, b1);
}

// ---------------------------------------------------------------------------
// Kernel 2: e_s per (p,s). One warp per pair-slot. grid=2048 x 128.
// ---------------------------------------------------------------------------
__global__ void es_kernel(const float* __restrict__ x,
                          const int* __restrict__ node_pairs,
                          const int* __restrict__ types) {
    int tid = threadIdx.x;
    int lane = tid & 31;
    int gw = blockIdx.x * 4 + (tid >> 5);   // ps index, 0..8191
    int node = node_pairs[gw];
    int t = types[node];
    const float4 x4 = *(const float4*)(x + (size_t)node * D + lane * 4);
    const float4 v4 = *(const float4*)(g_v + t * D + lane * 4);
    float part = x4.x * v4.x + x4.y * v4.y + x4.z * v4.z + x4.w * v4.w;
#pragma unroll
    for (int off = 16; off; off >>= 1)
        part += __shfl_xor_sync(0xffffffffu, part, off);
    if (lane == 0) g_es[gw] = part;
}

// ---------------------------------------------------------------------------
// Kernel 3: main — gather + softmax + aggregate (R10 structure, unchanged).
// ---------------------------------------------------------------------------
__global__ __launch_bounds__(128) void main_kernel(
    const float* __restrict__ x,
    const int* __restrict__ types,
    const int* __restrict__ nbr,
    const float* __restrict__ dt) {

    int p = blockIdx.x;
    int tid = threadIdx.x;
    int w = tid >> 5;       // r
    int lane = tid & 31;

    __shared__ __align__(16) float s_u[T * D];   // 1.5 KB
    s_u[tid]       = g_u[tid];
    s_u[tid + 128] = g_u[tid + 128];
    s_u[tid + 256] = g_u[tid + 256];

    int base0 = (p * 2 * R + w) * K;
    int base1 = base0 + R * K;

    int ni0 = 0, ni1 = 0, ty0 = 0, ty1 = 0;
    float edt0 = 0.f, edt1 = 0.f;
    if (lane < 16) {
        ni0 = nbr[base0 + lane];
        ni1 = nbr[base1 + lane];
        edt0 = __expf(-dt[base0 + lane]);
        edt1 = __expf(-dt[base1 + lane]);
        ty0 = types[ni0];
        ty1 = types[ni1];
    }
    float es0 = g_es[p * 2];
    float es1 = g_es[p * 2 + 1];
    __syncthreads();                 // s_u staged

    float4 hacc = make_float4(0.f, 0.f, 0.f, 0.f);

#pragma unroll
    for (int s = 0; s < 2; s++) {
        int   ni  = s ? ni1  : ni0;
        int   ty  = s ? ty1  : ty0;
        float edt = s ? edt1 : edt0;
        float es  = s ? es1  : es0;

        float sum = 0.f;
        float4 hs = make_float4(0.f, 0.f, 0.f, 0.f);

#pragma unroll
        for (int b = 0; b < 2; b++) {        // two batches of 8 neighbors
            float4 xv[8];
#pragma unroll
            for (int j = 0; j < 8; j++) {
                int nik = __shfl_sync(0xffffffffu, ni, b * 8 + j);
                xv[j] = *(const float4*)(x + (size_t)nik * D + lane * 4);
            }
#pragma unroll
            for (int j = 0; j < 8; j++) {
                int k = b * 8 + j;
                int tyk = __shfl_sync(0xffffffffu, ty, k);
                const float4 u4 = *(const float4*)&s_u[tyk * D + lane * 4];
                float d = xv[j].x * u4.x + xv[j].y * u4.y +
                          xv[j].z * u4.z + xv[j].w * u4.w;
#pragma unroll
                for (int off = 16; off; off >>= 1)
                    d += __shfl_xor_sync(0xffffffffu, d, off);
                float edtk = __shfl_sync(0xffffffffu, edt, k);
                float ex = __expf((d + es) * edtk);   // same value all lanes
                sum += ex;
                hs.x = fmaf(ex, xv[j].x, hs.x);
                hs.y = fmaf(ex, xv[j].y, hs.y);
                hs.z = fmaf(ex, xv[j].z, hs.z);
                hs.w = fmaf(ex, xv[j].w, hs.w);
            }
        }
        float inv = __fdividef(1.f, sum);
        hacc.x = fmaf(inv, hs.x, hacc.x);
        hacc.y = fmaf(inv, hs.y, hacc.y);
        hacc.z = fmaf(inv, hs.z, hacc.z);
        hacc.w = fmaf(inv, hs.w, hacc.w);
    }

    *(float4*)(g_g + (size_t)(p * R + w) * D + lane * 4) = hacc;
}

// ---------------------------------------------------------------------------
// Kernel 4: warp-level bf16 tensor-core out-GEMM + fused epilogue.
// C[4096,128] = G[4096,512] @ Wb[512,128]; out = sigmoid(0.125*(C + bias2)).
// 32 CTAs x 256 thr (8 warps). Warp = 16M x 128N strip; K = 32 tiles of 16.
// mma.sync.m16n8k16 bf16 (base sm_103 — NOT tcgen05). B fragments staged
// once in smem as pre-packed uint2 (one LDS.64 = b0+b1), row pad 132 makes
// each 16-lane LDS.64 phase conflict-free. A converted fp32->bf16 on the fly.
// ---------------------------------------------------------------------------
#define BROWPAD 132
#define SMEM_B_BYTES (128 * BROWPAD * 8)   // 135168

__global__ __launch_bounds__(256) void mma_out_kernel(float* __restrict__ out) {
    extern __shared__ uint2 s_b[];         // [128][BROWPAD]
    int tid = threadIdx.x;
    int w = tid >> 5;
    int lane = tid & 31;
    int g = lane >> 2;        // row-in-octet / B col group
    int t = lane & 3;         // k pair index

    // stage all of B (16384 uint2) via uint4 loads
    {
        const uint4* src = (const uint4*)g_wbQ;
#pragma unroll
        for (int i = tid; i < 8192; i += 256) {
            int row = i >> 6;
            int cp = (i & 63) * 2;
            uint4 v = src[i];
            *(uint4*)&s_b[row * BROWPAD + cp] = v;
        }
    }
    __syncthreads();

    int rm0 = blockIdx.x * 128 + w * 16 + g;   // fragment rows rm0, rm0+8
    const float* ga0 = g_g + (size_t)rm0 * (R * D) + t * 2;
    const float* ga1 = ga0 + 8 * (R * D);

    float acc[16][4];
#pragma unroll
    for (int nt = 0; nt < 16; nt++)
#pragma unroll
        for (int j = 0; j < 4; j++) acc[nt][j] = 0.f;

    for (int kt = 0; kt < 32; kt++) {
        // A fragments: float2 loads + bf16x2 convert
        float2 fa0 = *(const float2*)(ga0 + kt * 16);
        float2 fa1 = *(const float2*)(ga1 + kt * 16);
        float2 fa2 = *(const float2*)(ga0 + kt * 16 + 8);
        float2 fa3 = *(const float2*)(ga1 + kt * 16 + 8);
        uint32_t a0, a1, a2, a3;
        asm("cvt.rn.bf16x2.f32 %0, %1, %2;" : "=r"(a0) : "f"(fa0.y), "f"(fa0.x));
        asm("cvt.rn.bf16x2.f32 %0, %1, %2;" : "=r"(a1) : "f"(fa1.y), "f"(fa1.x));
        asm("cvt.rn.bf16x2.f32 %0, %1, %2;" : "=r"(a2) : "f"(fa2.y), "f"(fa2.x));
        asm("cvt.rn.bf16x2.f32 %0, %1, %2;" : "=r"(a3) : "f"(fa3.y), "f"(fa3.x));

        const uint2* brow = s_b + (kt * 4 + t) * BROWPAD + g;
#pragma unroll
        for (int nt = 0; nt < 16; nt++) {
            uint2 bq = brow[nt * 8];
            asm volatile(
                "mma.sync.aligned.m16n8k16.row.col.f32.bf16.bf16.f32 "
                "{%0,%1,%2,%3}, {%4,%5,%6,%7}, {%8,%9}, {%0,%1,%2,%3};"
                : "+f"(acc[nt][0]), "+f"(acc[nt][1]),
                  "+f"(acc[nt][2]), "+f"(acc[nt][3])
                : "r"(a0), "r"(a1), "r"(a2), "r"(a3),
                  "r"(bq.x), "r"(bq.y));
        }
    }

    // epilogue: bias + 0.125 scale + sigmoid, direct to out
    float* orow0 = out + (size_t)rm0 * D;
    float* orow1 = orow0 + 8 * D;
#pragma unroll
    for (int nt = 0; nt < 16; nt++) {
        int n0 = nt * 8 + t * 2;
        float b0v = g_bias2[n0];
        float b1v = g_bias2[n0 + 1];
        float v00 = 0.125f * (acc[nt][0] + b0v);
        float v01 = 0.125f * (acc[nt][1] + b1v);
        float v10 = 0.125f * (acc[nt][2] + b0v);
        float v11 = 0.125f * (acc[nt][3] + b1v);
        float2 o0, o1;
        o0.x = __fdividef(1.f, 1.f + __expf(-v00));
        o0.y = __fdividef(1.f, 1.f + __expf(-v01));
        o1.x = __fdividef(1.f, 1.f + __expf(-v10));
        o1.y = __fdividef(1.f, 1.f + __expf(-v11));
        *(float2*)(orow0 + n0) = o0;
        *(float2*)(orow1 + n0) = o1;
    }
}

// ---------------------------------------------------------------------------
// Launch
// ---------------------------------------------------------------------------
extern "C" void kernel_launch(void* const* d_in, const int* in_sizes, int n_in,
                              void* d_out, int out_size) {
    const float* node_embeds   = (const float*)d_in[0];
    const int*   node_pairs    = (const int*)d_in[1];
    const int*   node_type_ids = (const int*)d_in[2];
    const int*   neighbor_idx  = (const int*)d_in[3];
    const float* delta_t       = (const float*)d_in[4];
    const float* W_phi         = (const float*)d_in[5];
    const float* W_zeta        = (const float*)d_in[6];
    const float* W_beta_w      = (const float*)d_in[7];
    const float* W_beta_b      = (const float*)d_in[8];
    float* out = (float*)d_out;

    static bool attr_done = false;
    if (!attr_done) {
        cudaFuncSetAttribute(mma_out_kernel,
                             cudaFuncAttributeMaxDynamicSharedMemorySize,
                             SMEM_B_BYTES);
        attr_done = true;
    }

    prep_kernel<<<4, 128>>>(W_phi, W_zeta, W_beta_b);
    wbq_kernel<<<64, 256>>>(W_beta_w);
    es_kernel<<<(P * 2) / 4, 128>>>(node_embeds, node_pairs, node_type_ids);
    main_kernel<<<P, 128>>>(node_embeds, node_type_ids, neighbor_idx, delta_t);
    mma_out_kernel<<<P / 128, 256, SMEM_B_BYTES>>>(out);
}